// round 10
// baseline (speedup 1.0000x reference)
#include <cuda_runtime.h>
#include <cuda_bf16.h>
#include <math.h>

#define BB 4
#define CC_IN 128
#define HH 56
#define WW 56
#define HW 3136
#define MID 32
#define OG 512
#define COUT 128
#define GCN 4
#define K2 9
#define NPQ 28224
#define EPS 1e-5f

// ---------------- device scratch ----------------
__device__ float g_v [BB * OG * HW];
__device__ float g_hq[BB * MID * HW];
__device__ float g_hk[BB * MID * HW];
__device__ float g_Wkt [CC_IN * CC_IN];      // [c][d]
__device__ float g_W1qt[CC_IN * MID];        // [c][m]
__device__ float g_W1kt[CC_IN * MID];        // [c][m]
__device__ float g_Wvt [CC_IN * OG];         // [c][o]
__device__ float g_W2t [GCN * MID * COUT];   // [g][m][o]
__device__ float g_bke[CC_IN];
__device__ float g_bh [MID];
__device__ float g_bv [OG];
__device__ float g_M  [BB * MID * MID];
__device__ float g_Sh [BB * MID];
__device__ float g_c1 [BB * OG];
__device__ float g_c0 [BB * OG];

// Fold BN affines into (transposed) weights + zero M/Sh accumulators.
__global__ void fold_kernel(
    const float* __restrict__ Wk,
    const float* __restrict__ bn1g, const float* __restrict__ bn1b,
    const float* __restrict__ bn1m, const float* __restrict__ bn1v,
    const float* __restrict__ W1,  const float* __restrict__ b1,
    const float* __restrict__ bn2g, const float* __restrict__ bn2b,
    const float* __restrict__ bn2m, const float* __restrict__ bn2v,
    const float* __restrict__ W2,
    const float* __restrict__ Wv,
    const float* __restrict__ bnvg, const float* __restrict__ bnvb,
    const float* __restrict__ bnvm, const float* __restrict__ bnvv)
{
    int i = blockIdx.x * blockDim.x + threadIdx.x;
    if (i < 16384) {
        int d = i >> 7, c = i & 127;
        float s = bn1g[d] * rsqrtf(bn1v[d] + EPS);
        g_Wkt[c * 128 + d] = Wk[d * 128 + c] * s;
    } else if (i < 20480) {
        int j = i - 16384; int m = j >> 7, c = j & 127;
        float s = bn2g[m] * rsqrtf(bn2v[m] + EPS);
        g_W1qt[c * MID + m] = W1[m * 256 + c] * s;
    } else if (i < 24576) {
        int j = i - 20480; int m = j >> 7, c = j & 127;
        float s = bn2g[m] * rsqrtf(bn2v[m] + EPS);
        g_W1kt[c * MID + m] = W1[m * 256 + 128 + c] * s;
    } else if (i < 90112) {
        int j = i - 24576; int o = j >> 7, c = j & 127;
        float s = bnvg[o] * rsqrtf(bnvv[o] + EPS);
        g_Wvt[c * OG + o] = Wv[o * 128 + c] * s;
    } else if (i < 106496) {
        int j = i - 90112; int o = j & 127, t = j >> 7;
        int g = t >> 5, m = t & 31;
        g_W2t[(g * MID + m) * COUT + o] = W2[(o * GCN + g) * MID + m];
    } else if (i < 106624) {
        int d = i - 106496;
        float s = bn1g[d] * rsqrtf(bn1v[d] + EPS);
        g_bke[d] = bn1b[d] - bn1m[d] * s;
    } else if (i < 106656) {
        int m = i - 106624;
        float s = bn2g[m] * rsqrtf(bn2v[m] + EPS);
        g_bh[m] = s * b1[m] + bn2b[m] - bn2m[m] * s;
    } else if (i < 107168) {
        int o = i - 106656;
        float s = bnvg[o] * rsqrtf(bnvv[o] + EPS);
        g_bv[o] = bnvb[o] - bnvm[o] * s;
    } else if (i < 111264) {
        g_M[i - 107168] = 0.f;
    } else if (i < 111392) {
        g_Sh[i - 111264] = 0.f;
    }
}

// ---------------- front kernel: ke (regs/smem only) + hq + hk in one pass ----------------
__global__ void __launch_bounds__(256) front_kernel(
    const float* __restrict__ X,
    float* __restrict__ hq_out, float* __restrict__ hk_out)
{
    extern __shared__ float fsm[];
    float* sX   = fsm;            // 4096
    float* sWk  = fsm + 4096;     // 8192
    float* sW1q = fsm + 12288;    // 2048
    float* sW1k = fsm;            // overlay of sX
    float* sKE  = fsm + 4096;     // overlay of sWk
    const int b   = blockIdx.y;
    const int hw0 = blockIdx.x * 64;
    const int tid = threadIdx.x;
    const int tx  = tid & 15;
    const int td  = tid >> 4;

    float keacc[8][4];
    float hqacc[2][4];
    #pragma unroll
    for (int j = 0; j < 8; j++)
        #pragma unroll
        for (int i = 0; i < 4; i++) keacc[j][i] = 0.f;
    #pragma unroll
    for (int j = 0; j < 2; j++)
        #pragma unroll
        for (int i = 0; i < 4; i++) hqacc[j][i] = 0.f;

    const float* Xb = X + (size_t)b * CC_IN * HW;
    for (int cc = 0; cc < 128; cc += 64) {
        for (int k = tid; k < 1024; k += 256) {
            int c = k >> 4, q = k & 15;
            *(float4*)&sX[c * 64 + q * 4] = *(const float4*)&Xb[(size_t)(cc + c) * HW + hw0 + q * 4];
        }
        for (int k = tid; k < 2048; k += 256) {
            int c = k >> 5, q = k & 31;
            *(float4*)&sWk[c * 128 + q * 4] = *(const float4*)&g_Wkt[(cc + c) * 128 + q * 4];
        }
        for (int k = tid; k < 512; k += 256) {
            int c = k >> 3, q = k & 7;
            *(float4*)&sW1q[c * 32 + q * 4] = *(const float4*)&g_W1qt[(cc + c) * 32 + q * 4];
        }
        __syncthreads();
        #pragma unroll 4
        for (int c = 0; c < 64; c++) {
            float4 xv = *(const float4*)&sX[c * 64 + 4 * tx];
            float4 w0 = *(const float4*)&sWk[c * 128 + 8 * td];
            float4 w1 = *(const float4*)&sWk[c * 128 + 8 * td + 4];
            keacc[0][0] = fmaf(w0.x, xv.x, keacc[0][0]); keacc[0][1] = fmaf(w0.x, xv.y, keacc[0][1]);
            keacc[0][2] = fmaf(w0.x, xv.z, keacc[0][2]); keacc[0][3] = fmaf(w0.x, xv.w, keacc[0][3]);
            keacc[1][0] = fmaf(w0.y, xv.x, keacc[1][0]); keacc[1][1] = fmaf(w0.y, xv.y, keacc[1][1]);
            keacc[1][2] = fmaf(w0.y, xv.z, keacc[1][2]); keacc[1][3] = fmaf(w0.y, xv.w, keacc[1][3]);
            keacc[2][0] = fmaf(w0.z, xv.x, keacc[2][0]); keacc[2][1] = fmaf(w0.z, xv.y, keacc[2][1]);
            keacc[2][2] = fmaf(w0.z, xv.z, keacc[2][2]); keacc[2][3] = fmaf(w0.z, xv.w, keacc[2][3]);
            keacc[3][0] = fmaf(w0.w, xv.x, keacc[3][0]); keacc[3][1] = fmaf(w0.w, xv.y, keacc[3][1]);
            keacc[3][2] = fmaf(w0.w, xv.z, keacc[3][2]); keacc[3][3] = fmaf(w0.w, xv.w, keacc[3][3]);
            keacc[4][0] = fmaf(w1.x, xv.x, keacc[4][0]); keacc[4][1] = fmaf(w1.x, xv.y, keacc[4][1]);
            keacc[4][2] = fmaf(w1.x, xv.z, keacc[4][2]); keacc[4][3] = fmaf(w1.x, xv.w, keacc[4][3]);
            keacc[5][0] = fmaf(w1.y, xv.x, keacc[5][0]); keacc[5][1] = fmaf(w1.y, xv.y, keacc[5][1]);
            keacc[5][2] = fmaf(w1.y, xv.z, keacc[5][2]); keacc[5][3] = fmaf(w1.y, xv.w, keacc[5][3]);
            keacc[6][0] = fmaf(w1.z, xv.x, keacc[6][0]); keacc[6][1] = fmaf(w1.z, xv.y, keacc[6][1]);
            keacc[6][2] = fmaf(w1.z, xv.z, keacc[6][2]); keacc[6][3] = fmaf(w1.z, xv.w, keacc[6][3]);
            keacc[7][0] = fmaf(w1.w, xv.x, keacc[7][0]); keacc[7][1] = fmaf(w1.w, xv.y, keacc[7][1]);
            keacc[7][2] = fmaf(w1.w, xv.z, keacc[7][2]); keacc[7][3] = fmaf(w1.w, xv.w, keacc[7][3]);
            float2 wq = *(const float2*)&sW1q[c * 32 + 2 * td];
            hqacc[0][0] = fmaf(wq.x, xv.x, hqacc[0][0]); hqacc[0][1] = fmaf(wq.x, xv.y, hqacc[0][1]);
            hqacc[0][2] = fmaf(wq.x, xv.z, hqacc[0][2]); hqacc[0][3] = fmaf(wq.x, xv.w, hqacc[0][3]);
            hqacc[1][0] = fmaf(wq.y, xv.x, hqacc[1][0]); hqacc[1][1] = fmaf(wq.y, xv.y, hqacc[1][1]);
            hqacc[1][2] = fmaf(wq.y, xv.z, hqacc[1][2]); hqacc[1][3] = fmaf(wq.y, xv.w, hqacc[1][3]);
        }
        __syncthreads();
    }
    #pragma unroll
    for (int j = 0; j < 2; j++) {
        int m = 2 * td + j;
        float4 r; r.x = hqacc[j][0]; r.y = hqacc[j][1]; r.z = hqacc[j][2]; r.w = hqacc[j][3];
        *(float4*)&hq_out[((size_t)b * MID + m) * HW + hw0 + 4 * tx] = r;
    }
    #pragma unroll
    for (int j = 0; j < 8; j++) {
        int d = 8 * td + j;
        float bsv = g_bke[d];
        float4 r;
        r.x = fmaxf(keacc[j][0] + bsv, 0.f); r.y = fmaxf(keacc[j][1] + bsv, 0.f);
        r.z = fmaxf(keacc[j][2] + bsv, 0.f); r.w = fmaxf(keacc[j][3] + bsv, 0.f);
        *(float4*)&sKE[d * 64 + 4 * tx] = r;
    }
    for (int k = tid; k < 1024; k += 256) {
        int c = k >> 3, q = k & 7;
        *(float4*)&sW1k[c * 32 + q * 4] = *(const float4*)&g_W1kt[c * 32 + q * 4];
    }
    __syncthreads();
    float hkacc[2][4];
    #pragma unroll
    for (int j = 0; j < 2; j++)
        #pragma unroll
        for (int i = 0; i < 4; i++) hkacc[j][i] = 0.f;
    #pragma unroll 4
    for (int c = 0; c < 128; c++) {
        float4 hv = *(const float4*)&sKE[c * 64 + 4 * tx];
        float2 w = *(const float2*)&sW1k[c * 32 + 2 * td];
        hkacc[0][0] = fmaf(w.x, hv.x, hkacc[0][0]); hkacc[0][1] = fmaf(w.x, hv.y, hkacc[0][1]);
        hkacc[0][2] = fmaf(w.x, hv.z, hkacc[0][2]); hkacc[0][3] = fmaf(w.x, hv.w, hkacc[0][3]);
        hkacc[1][0] = fmaf(w.y, hv.x, hkacc[1][0]); hkacc[1][1] = fmaf(w.y, hv.y, hkacc[1][1]);
        hkacc[1][2] = fmaf(w.y, hv.z, hkacc[1][2]); hkacc[1][3] = fmaf(w.y, hv.w, hkacc[1][3]);
    }
    #pragma unroll
    for (int j = 0; j < 2; j++) {
        int m = 2 * td + j;
        float4 r; r.x = hkacc[j][0]; r.y = hkacc[j][1]; r.z = hkacc[j][2]; r.w = hkacc[j][3];
        *(float4*)&hk_out[((size_t)b * MID + m) * HW + hw0 + 4 * tx] = r;
    }
}

// ---------------- pointwise-conv GEMM (Wv): 128 threads, 8 d x 4 px ----------------
template<int DTILE, bool RELU>
__global__ void __launch_bounds__(128) pw_conv_kernel(
    const float* __restrict__ X, const float* __restrict__ Wt,
    const float* __restrict__ bias, float* __restrict__ Y, int Dtot)
{
    constexpr int PX = 64;
    constexpr int CCH = 64;
    constexpr int DN = DTILE / 8;
    __shared__ float sX[CCH * PX];
    __shared__ float sW[CCH * DTILE];
    const int b   = blockIdx.z;
    const int hw0 = blockIdx.x * PX;
    const int d0  = blockIdx.y * DTILE;
    const int tid = threadIdx.x;
    const int tx  = tid & 15;
    const int td  = tid >> 4;
    float acc[DN][4];
    #pragma unroll
    for (int j = 0; j < DN; j++)
        #pragma unroll
        for (int i = 0; i < 4; i++) acc[j][i] = 0.f;
    const float* Xb = X + (size_t)b * CC_IN * HW;
    for (int cc = 0; cc < CC_IN; cc += CCH) {
        for (int k = tid; k < CCH * PX / 4; k += 128) {
            int c = k >> 4, q = k & 15;
            *(float4*)&sX[c * 64 + q * 4] = *(const float4*)&Xb[(size_t)(cc + c) * HW + hw0 + q * 4];
        }
        for (int k = tid; k < CCH * DTILE / 4; k += 128) {
            int c = k / (DTILE / 4), q = k % (DTILE / 4);
            *(float4*)&sW[c * DTILE + q * 4] = *(const float4*)&Wt[(size_t)(cc + c) * Dtot + d0 + q * 4];
        }
        __syncthreads();
        #pragma unroll 4
        for (int c = 0; c < CCH; c++) {
            float4 xv = *(const float4*)&sX[c * 64 + 4 * tx];
            float4 w0 = *(const float4*)&sW[c * DTILE + DN * td];
            acc[0][0] = fmaf(w0.x, xv.x, acc[0][0]); acc[0][1] = fmaf(w0.x, xv.y, acc[0][1]);
            acc[0][2] = fmaf(w0.x, xv.z, acc[0][2]); acc[0][3] = fmaf(w0.x, xv.w, acc[0][3]);
            acc[1][0] = fmaf(w0.y, xv.x, acc[1][0]); acc[1][1] = fmaf(w0.y, xv.y, acc[1][1]);
            acc[1][2] = fmaf(w0.y, xv.z, acc[1][2]); acc[1][3] = fmaf(w0.y, xv.w, acc[1][3]);
            acc[2][0] = fmaf(w0.z, xv.x, acc[2][0]); acc[2][1] = fmaf(w0.z, xv.y, acc[2][1]);
            acc[2][2] = fmaf(w0.z, xv.z, acc[2][2]); acc[2][3] = fmaf(w0.z, xv.w, acc[2][3]);
            acc[3][0] = fmaf(w0.w, xv.x, acc[3][0]); acc[3][1] = fmaf(w0.w, xv.y, acc[3][1]);
            acc[3][2] = fmaf(w0.w, xv.z, acc[3][2]); acc[3][3] = fmaf(w0.w, xv.w, acc[3][3]);
            if (DN == 8) {
                float4 w1 = *(const float4*)&sW[c * DTILE + DN * td + 4];
                acc[4][0] = fmaf(w1.x, xv.x, acc[4][0]); acc[4][1] = fmaf(w1.x, xv.y, acc[4][1]);
                acc[4][2] = fmaf(w1.x, xv.z, acc[4][2]); acc[4][3] = fmaf(w1.x, xv.w, acc[4][3]);
                acc[5][0] = fmaf(w1.y, xv.x, acc[5][0]); acc[5][1] = fmaf(w1.y, xv.y, acc[5][1]);
                acc[5][2] = fmaf(w1.y, xv.z, acc[5][2]); acc[5][3] = fmaf(w1.y, xv.w, acc[5][3]);
                acc[6][0] = fmaf(w1.z, xv.x, acc[6][0]); acc[6][1] = fmaf(w1.z, xv.y, acc[6][1]);
                acc[6][2] = fmaf(w1.z, xv.z, acc[6][2]); acc[6][3] = fmaf(w1.z, xv.w, acc[6][3]);
                acc[7][0] = fmaf(w1.w, xv.x, acc[7][0]); acc[7][1] = fmaf(w1.w, xv.y, acc[7][1]);
                acc[7][2] = fmaf(w1.w, xv.z, acc[7][2]); acc[7][3] = fmaf(w1.w, xv.w, acc[7][3]);
            }
        }
        __syncthreads();
    }
    #pragma unroll
    for (int j = 0; j < DN; j++) {
        int d = d0 + td * DN + j;
        float bsv = bias ? bias[d] : 0.f;
        float4 r;
        r.x = acc[j][0] + bsv; r.y = acc[j][1] + bsv;
        r.z = acc[j][2] + bsv; r.w = acc[j][3] + bsv;
        if (RELU) {
            r.x = fmaxf(r.x, 0.f); r.y = fmaxf(r.y, 0.f);
            r.z = fmaxf(r.z, 0.f); r.w = fmaxf(r.w, 0.f);
        }
        *(float4*)&Y[((size_t)b * Dtot + d) * HW + hw0 + 4 * tx] = r;
    }
}

// ---------------- stats: build 3 dj planes once, SYRK, atomics (R9 version) ----------------
__global__ void __launch_bounds__(256) stats_gram_kernel(
    const float* __restrict__ hq, const float* __restrict__ hk,
    const float* __restrict__ bh,
    float* __restrict__ M, float* __restrict__ Sh)
{
    __shared__ float s_hq[32 * 56];
    __shared__ float s_hk[32 * 58];
    __shared__ float sHp [3 * 56 * 32];
    __shared__ float sSh [32];
    __shared__ float sM  [1024];
    const int y  = blockIdx.x;
    const int di = blockIdx.y;
    const int b  = blockIdx.z;
    const int tid = threadIdx.x;
    const int mloc = tid & 31;
    if (tid < 32) sSh[tid] = 0.f;
    for (int k = tid; k < 1024; k += 256) sM[k] = 0.f;
    for (int k = tid; k < 1792; k += 256) {
        int m = k / 56, x = k % 56;
        s_hq[m * 56 + x] = hq[((size_t)b * MID + m) * HW + y * WW + x];
    }
    const int yk = y + di - 1;
    const bool rowin = (yk >= 0 && yk < HH);
    for (int k = tid; k < 1856; k += 256) {
        int m = k / 58, xi = k % 58;
        int xp = xi - 1;
        s_hk[k] = (rowin && xp >= 0 && xp < WW)
                 ? hk[((size_t)b * MID + m) * HW + yk * WW + xp] : 0.f;
    }
    __syncthreads();
    const float bhm = bh[mloc];
    float shsum = 0.f;
    for (int k = tid; k < 5376; k += 256) {
        int xdj = k >> 5;
        int dj = xdj / 56, x = xdj % 56;
        float v = fmaxf(s_hq[mloc * 56 + x] + s_hk[mloc * 58 + x + dj] + bhm, 0.f);
        sHp[k] = v;
        shsum += v;
    }
    __syncthreads();
    const int combo = tid & 63;
    const int it = combo & 7, jt = combo >> 3;
    const int pg = tid >> 6;
    float accM[4][4];
    #pragma unroll
    for (int a = 0; a < 4; a++)
        #pragma unroll
        for (int c = 0; c < 4; c++) accM[a][c] = 0.f;
    #pragma unroll 2
    for (int px = pg * 42; px < pg * 42 + 42; px++) {
        float4 hi = *(const float4*)&sHp[px * 32 + it * 4];
        float4 hj = *(const float4*)&sHp[px * 32 + jt * 4];
        accM[0][0] = fmaf(hi.x, hj.x, accM[0][0]); accM[0][1] = fmaf(hi.x, hj.y, accM[0][1]);
        accM[0][2] = fmaf(hi.x, hj.z, accM[0][2]); accM[0][3] = fmaf(hi.x, hj.w, accM[0][3]);
        accM[1][0] = fmaf(hi.y, hj.x, accM[1][0]); accM[1][1] = fmaf(hi.y, hj.y, accM[1][1]);
        accM[1][2] = fmaf(hi.y, hj.z, accM[1][2]); accM[1][3] = fmaf(hi.y, hj.w, accM[1][3]);
        accM[2][0] = fmaf(hi.z, hj.x, accM[2][0]); accM[2][1] = fmaf(hi.z, hj.y, accM[2][1]);
        accM[2][2] = fmaf(hi.z, hj.z, accM[2][2]); accM[2][3] = fmaf(hi.z, hj.w, accM[2][3]);
        accM[3][0] = fmaf(hi.w, hj.x, accM[3][0]); accM[3][1] = fmaf(hi.w, hj.y, accM[3][1]);
        accM[3][2] = fmaf(hi.w, hj.z, accM[3][2]); accM[3][3] = fmaf(hi.w, hj.w, accM[3][3]);
    }
    atomicAdd(&sSh[mloc], shsum);
    #pragma unroll
    for (int a = 0; a < 4; a++)
        #pragma unroll
        for (int c = 0; c < 4; c++)
            atomicAdd(&sM[(it * 4 + a) * 32 + jt * 4 + c], accM[a][c]);
    __syncthreads();
    if (tid < 32) atomicAdd(&Sh[b * 32 + tid], sSh[tid]);
    for (int k = tid; k < 1024; k += 256) atomicAdd(&M[b * 1024 + k], sM[k]);
}

// ---------------- GroupNorm stats -> precomputed GN affine (c1, c0) ----------------
__global__ void stats_kernel(const float* __restrict__ W2, const float* __restrict__ b2,
                             const float* __restrict__ gng, const float* __restrict__ gnb,
                             const float* __restrict__ M, const float* __restrict__ Sh,
                             float* __restrict__ c1out, float* __restrict__ c0out)
{
    int b = blockIdx.x, o = threadIdx.x;
    __shared__ float sM[1024], sSh[32];
    for (int k = o; k < 1024; k += 128) sM[k] = M[b * 1024 + k];
    if (o < 32) sSh[o] = Sh[b * 32 + o];
    __syncthreads();
    float S1 = 0.f, S2 = 0.f;
    const float NPf = (float)NPQ;
    for (int g = 0; g < GCN; g++) {
        int og = o * GCN + g;
        float w[32];
        #pragma unroll
        for (int m = 0; m < 32; m++) w[m] = W2[og * 32 + m];
        float d1 = 0.f;
        #pragma unroll
        for (int m = 0; m < 32; m++) d1 = fmaf(w[m], sSh[m], d1);
        float q = 0.f;
        for (int i2 = 0; i2 < 32; i2++) {
            float ti = 0.f;
            #pragma unroll
            for (int j = 0; j < 32; j++) ti = fmaf(sM[i2 * 32 + j], w[j], ti);
            q = fmaf(w[i2], ti, q);
        }
        float bbv = b2[og];
        S1 += d1 + bbv * NPf;
        S2 += q + 2.f * bbv * d1 + bbv * bbv * NPf;
    }
    const float N = (float)(GCN * NPQ);
    float m_ = S1 / N;
    float var = S2 / N - m_ * m_;
    float rinv = rsqrtf(var + EPS);
    #pragma unroll
    for (int g = 0; g < GCN; g++) {
        int og = o * GCN + g;
        float c1 = rinv * gng[og];
        float c0 = c1 * b2[og] + gnb[og] - m_ * c1;
        c1out[b * OG + og] = c1;
        c0out[b * OG + og] = c0;
    }
}

// ---------------- main fused kernel: 9-plane sH, register-prefetch V/W pipeline ----------------
// grid (7, 14, B*2). 128 threads, 4 o x 4 px per thread, 64 couts per block.
// smem: sH 9216 | sV 3968 | sWt 2176 = 15360 fl = 61440 B -> 3 blocks/SM
__global__ void __launch_bounds__(128, 3) main_kernel(
    const float* __restrict__ hq, const float* __restrict__ hk,
    const float* __restrict__ v,
    const float* __restrict__ W2t,
    const float* __restrict__ c1arr, const float* __restrict__ c0arr,
    const float* __restrict__ bh, float* __restrict__ out)
{
    extern __shared__ float smem[];
    float* sH  = smem;                 // 9216
    float* sV  = smem + 9216;          // 3968
    float* sWt = smem + 13184;         // 2176
    float* s_hq = sV;                  // staging overlay (1024)
    float* s_hk = sV + 1024;           // staging overlay (1920)
    const int bz  = blockIdx.z;
    const int b   = bz >> 1;
    const int ob0 = (bz & 1) * 64;
    const int x0  = blockIdx.x * 8;
    const int y0  = blockIdx.y * 4;
    const int tid = threadIdx.x;
    const int tq  = tid & 7;
    const int to  = tid >> 3;
    const int ly  = tq >> 1;
    const int lx0 = (tq & 1) * 4;

    const float* vb = v + (size_t)b * OG * HW;
    // prefetch layout: V -> thread owns o=tid>>1, s = (tid&1)*30 + i (3 rows x 10 cols of halo)
    const int vo  = tid >> 1;
    const int vy0 = (tid & 1) * 3;     // halo row base
    // W2t -> thread owns m=tid>>2, o0=(tid&3)*16, 16 contiguous couts (4 float4)
    const int wm  = tid >> 2;
    const int wo0 = (tid & 3) * 16;

    float vpre[30];
    float4 wpre[4];
    // issue g=0 prefetch immediately (overlaps with s_hq/s_hk staging + sH build)
    {
        const float* vrow = vb + (size_t)((ob0 + vo) * GCN + 0) * HW;
        #pragma unroll
        for (int yy = 0; yy < 3; yy++) {
            int gy = y0 - 1 + vy0 + yy;
            #pragma unroll
            for (int xx = 0; xx < 10; xx++) {
                int gx = x0 - 1 + xx;
                vpre[yy * 10 + xx] = (gy >= 0 && gy < HH && gx >= 0 && gx < WW)
                                     ? vrow[gy * WW + gx] : 0.f;
            }
        }
        const float* wrow = W2t + (0 * MID + wm) * COUT + ob0 + wo0;
        #pragma unroll
        for (int j = 0; j < 4; j++) wpre[j] = *(const float4*)&wrow[j * 4];
    }

    const float bhv = (tid < 32) ? bh[tid] : 0.f;   // unused lanes ok
    // stage hq (+bh folded) and hk halo
    for (int k = tid; k < 1024; k += 128) {
        int m = k >> 5, px = k & 31, lyy = px >> 3, lxx = px & 7;
        s_hq[k] = hq[((size_t)b * MID + m) * HW + (y0 + lyy) * WW + x0 + lxx] + bh[m];
    }
    for (int k = tid; k < 1920; k += 128) {
        int m = k / 60, s = k % 60, yy = s / 10, xx = s % 10;
        int gy = y0 - 1 + yy, gx = x0 - 1 + xx;
        s_hk[k] = (gy >= 0 && gy < HH && gx >= 0 && gx < WW)
                  ? hk[((size_t)b * MID + m) * HW + gy * WW + gx] : 0.f;
    }
    __syncthreads();
    for (int k = tid; k < 9216; k += 128) {
        int p = k >> 10, m = (k >> 5) & 31, px = k & 31;
        int lyy = px >> 3, lxx = px & 7;
        int di = p / 3, dj = p % 3;
        float val = s_hq[m * 32 + px] + s_hk[m * 60 + (lyy + di) * 10 + (lxx + dj)];
        sH[k] = fmaxf(val, 0.f);
    }

    float acc[4][4];
    #pragma unroll
    for (int oo = 0; oo < 4; oo++)
        #pragma unroll
        for (int i = 0; i < 4; i++) acc[oo][i] = 0.f;

    for (int g = 0; g < GCN; g++) {
        __syncthreads();   // sH build done (g=0) / previous m-loop reads done
        // store prefetched data to smem
        #pragma unroll
        for (int i = 0; i < 30; i++) sV[vo * 62 + (tid & 1) * 30 + i] = vpre[i];
        #pragma unroll
        for (int j = 0; j < 4; j++) *(float4*)&sWt[wm * 68 + wo0 + j * 4] = wpre[j];
        // load GN affine for this g (L2-hot, tiny)
        float c1r[4], c0r[4];
        #pragma unroll
        for (int oo = 0; oo < 4; oo++) {
            int og = (ob0 + to * 4 + oo) * GCN + g;
            c1r[oo] = c1arr[b * OG + og];
            c0r[oo] = c0arr[b * OG + og];
        }
        // issue next-g prefetch (latency hidden under this g's compute)
        if (g < GCN - 1) {
            const float* vrow = vb + (size_t)((ob0 + vo) * GCN + g + 1) * HW;
            #pragma unroll
            for (int yy = 0; yy < 3; yy++) {
                int gy = y0 - 1 + vy0 + yy;
                #pragma unroll
                for (int xx = 0; xx < 10; xx++) {
                    int gx = x0 - 1 + xx;
                    vpre[yy * 10 + xx] = (gy >= 0 && gy < HH && gx >= 0 && gx < WW)
                                         ? vrow[gy * WW + gx] : 0.f;
                }
            }
            const float* wrow = W2t + ((g + 1) * MID + wm) * COUT + ob0 + wo0;
            #pragma unroll
            for (int j = 0; j < 4; j++) wpre[j] = *(const float4*)&wrow[j * 4];
        }
        __syncthreads();

        #pragma unroll
        for (int sweep = 0; sweep < 3; sweep++) {
            float aacc[3][4][4];
            #pragma unroll
            for (int pp = 0; pp < 3; pp++)
                #pragma unroll
                for (int oo = 0; oo < 4; oo++)
                    #pragma unroll
                    for (int i = 0; i < 4; i++) aacc[pp][oo][i] = 0.f;
            #pragma unroll 8
            for (int m = 0; m < 32; m++) {
                float4 w = *(const float4*)&sWt[m * 68 + 4 * to];
                #pragma unroll
                for (int pp = 0; pp < 3; pp++) {
                    float4 hv = *(const float4*)&sH[((sweep * 3 + pp) << 10) + (m << 5) + 4 * tq];
                    float* a0 = &aacc[pp][0][0];
                    a0[0]  = fmaf(w.x, hv.x, a0[0]);  a0[1]  = fmaf(w.x, hv.y, a0[1]);
                    a0[2]  = fmaf(w.x, hv.z, a0[2]);  a0[3]  = fmaf(w.x, hv.w, a0[3]);
                    a0[4]  = fmaf(w.y, hv.x, a0[4]);  a0[5]  = fmaf(w.y, hv.y, a0[5]);
                    a0[6]  = fmaf(w.y, hv.z, a0[6]);  a0[7]  = fmaf(w.y, hv.w, a0[7]);
                    a0[8]  = fmaf(w.z, hv.x, a0[8]);  a0[9]  = fmaf(w.z, hv.y, a0[9]);
                    a0[10] = fmaf(w.z, hv.z, a0[10]); a0[11] = fmaf(w.z, hv.w, a0[11]);
                    a0[12] = fmaf(w.w, hv.x, a0[12]); a0[13] = fmaf(w.w, hv.y, a0[13]);
                    a0[14] = fmaf(w.w, hv.z, a0[14]); a0[15] = fmaf(w.w, hv.w, a0[15]);
                }
            }
            #pragma unroll
            for (int pp = 0; pp < 3; pp++) {
                #pragma unroll
                for (int oo = 0; oo < 4; oo++) {
                    float c1 = c1r[oo], c0 = c0r[oo];
                    int ol = to * 4 + oo;
                    #pragma unroll
                    for (int i = 0; i < 4; i++) {
                        float Vv = sV[ol * 62 + (ly + sweep) * 10 + (lx0 + i + pp)];
                        float t = fmaf(c1, aacc[pp][oo][i], c0);
                        acc[oo][i] = fmaf(t, Vv, acc[oo][i]);
                    }
                }
            }
        }
    }
    #pragma unroll
    for (int oo = 0; oo < 4; oo++) {
        float4 r;
        r.x = acc[oo][0]; r.y = acc[oo][1]; r.z = acc[oo][2]; r.w = acc[oo][3];
        *(float4*)&out[((size_t)b * COUT + ob0 + to * 4 + oo) * HW + (y0 + ly) * WW + x0 + lx0] = r;
    }
    (void)bhv;
}

// ---------------- launch ----------------
extern "C" void kernel_launch(void* const* d_in, const int* in_sizes, int n_in,
                              void* d_out, int out_size)
{
    const float* x     = (const float*)d_in[0];
    const float* Wk    = (const float*)d_in[1];
    const float* bn1g  = (const float*)d_in[2];
    const float* bn1b  = (const float*)d_in[3];
    const float* bn1m  = (const float*)d_in[4];
    const float* bn1v  = (const float*)d_in[5];
    const float* W1    = (const float*)d_in[6];
    const float* b1    = (const float*)d_in[7];
    const float* bn2g  = (const float*)d_in[8];
    const float* bn2b  = (const float*)d_in[9];
    const float* bn2m  = (const float*)d_in[10];
    const float* bn2v  = (const float*)d_in[11];
    const float* W2    = (const float*)d_in[12];
    const float* b2    = (const float*)d_in[13];
    const float* gng   = (const float*)d_in[14];
    const float* gnb   = (const float*)d_in[15];
    const float* Wv    = (const float*)d_in[16];
    const float* bnvg  = (const float*)d_in[17];
    const float* bnvb  = (const float*)d_in[18];
    const float* bnvm  = (const float*)d_in[19];
    const float* bnvv  = (const float*)d_in[20];
    float* out = (float*)d_out;

    float *vv, *hq, *hk, *pM, *pSh, *pc1, *pc0;
    float *pWvt, *pW2t, *pbv, *pbh;
    cudaGetSymbolAddress((void**)&vv,    g_v);
    cudaGetSymbolAddress((void**)&hq,    g_hq);
    cudaGetSymbolAddress((void**)&hk,    g_hk);
    cudaGetSymbolAddress((void**)&pM,    g_M);
    cudaGetSymbolAddress((void**)&pSh,   g_Sh);
    cudaGetSymbolAddress((void**)&pc1,   g_c1);
    cudaGetSymbolAddress((void**)&pc0,   g_c0);
    cudaGetSymbolAddress((void**)&pWvt,  g_Wvt);
    cudaGetSymbolAddress((void**)&pW2t,  g_W2t);
    cudaGetSymbolAddress((void**)&pbv,   g_bv);
    cudaGetSymbolAddress((void**)&pbh,   g_bh);

    static cudaStream_t s2 = nullptr;
    static cudaEvent_t evFork = nullptr, evJoin = nullptr;
    static bool init_done = false;
    if (!init_done) {
        cudaFuncSetAttribute(main_kernel,  cudaFuncAttributeMaxDynamicSharedMemorySize, 61440);
        cudaFuncSetAttribute(front_kernel, cudaFuncAttributeMaxDynamicSharedMemorySize, 57344);
        cudaStreamCreateWithFlags(&s2, cudaStreamNonBlocking);
        cudaEventCreateWithFlags(&evFork, cudaEventDisableTiming);
        cudaEventCreateWithFlags(&evJoin, cudaEventDisableTiming);
        init_done = true;
    }

    fold_kernel<<<(111392 + 255) / 256, 256>>>(Wk, bn1g, bn1b, bn1m, bn1v,
                                               W1, b1, bn2g, bn2b, bn2m, bn2v,
                                               W2, Wv, bnvg, bnvb, bnvm, bnvv);
    // fork: Wv GEMM runs on s2 concurrently with front + stats chain
    cudaEventRecord(evFork, 0);
    cudaStreamWaitEvent(s2, evFork, 0);
    pw_conv_kernel<64, false><<<dim3(49, 8, BB), 128, 0, s2>>>(x, pWvt, pbv, vv, OG);
    cudaEventRecord(evJoin, s2);

    front_kernel<<<dim3(49, BB), 256, 57344>>>(x, hq, hk);
    stats_gram_kernel<<<dim3(56, 3, BB), 256>>>(hq, hk, pbh, pM, pSh);
    stats_kernel<<<BB, 128>>>(W2, b2, gng, gnb, pM, pSh, pc1, pc0);

    // join: main needs v from s2
    cudaStreamWaitEvent(0, evJoin, 0);
    main_kernel<<<dim3(7, 14, BB * 2), 128, 61440>>>(hq, hk, vv, pW2t, pc1, pc0, pbh, out);
}

// round 11
// speedup vs baseline: 1.0273x; 1.0273x over previous
#include <cuda_runtime.h>
#include <cuda_bf16.h>
#include <math.h>

#define BB 4
#define CC_IN 128
#define HH 56
#define WW 56
#define HW 3136
#define MID 32
#define OG 512
#define COUT 128
#define GCN 4
#define K2 9
#define NPQ 28224
#define EPS 1e-5f

// ---------------- device scratch ----------------
__device__ float g_v [BB * OG * HW];
__device__ float g_hq[BB * MID * HW];
__device__ float g_hk[BB * MID * HW];
__device__ float g_Wkt [CC_IN * CC_IN];      // [c][d]
__device__ float g_W1qt[CC_IN * MID];        // [c][m]
__device__ float g_W1kt[CC_IN * MID];        // [c][m]
__device__ float g_Wvt [CC_IN * OG];         // [c][o]
__device__ float g_W2t [GCN * MID * COUT];   // [g][m][o]
__device__ float g_bke[CC_IN];
__device__ float g_bh [MID];
__device__ float g_bv [OG];
__device__ float g_M  [BB * MID * MID];
__device__ float g_Sh [BB * MID];
__device__ float g_c1 [BB * OG];
__device__ float g_c0 [BB * OG];

// Fold BN affines into (transposed) weights + zero M/Sh accumulators.
__global__ void fold_kernel(
    const float* __restrict__ Wk,
    const float* __restrict__ bn1g, const float* __restrict__ bn1b,
    const float* __restrict__ bn1m, const float* __restrict__ bn1v,
    const float* __restrict__ W1,  const float* __restrict__ b1,
    const float* __restrict__ bn2g, const float* __restrict__ bn2b,
    const float* __restrict__ bn2m, const float* __restrict__ bn2v,
    const float* __restrict__ W2,
    const float* __restrict__ Wv,
    const float* __restrict__ bnvg, const float* __restrict__ bnvb,
    const float* __restrict__ bnvm, const float* __restrict__ bnvv)
{
    int i = blockIdx.x * blockDim.x + threadIdx.x;
    if (i < 16384) {
        int d = i >> 7, c = i & 127;
        float s = bn1g[d] * rsqrtf(bn1v[d] + EPS);
        g_Wkt[c * 128 + d] = Wk[d * 128 + c] * s;
    } else if (i < 20480) {
        int j = i - 16384; int m = j >> 7, c = j & 127;
        float s = bn2g[m] * rsqrtf(bn2v[m] + EPS);
        g_W1qt[c * MID + m] = W1[m * 256 + c] * s;
    } else if (i < 24576) {
        int j = i - 20480; int m = j >> 7, c = j & 127;
        float s = bn2g[m] * rsqrtf(bn2v[m] + EPS);
        g_W1kt[c * MID + m] = W1[m * 256 + 128 + c] * s;
    } else if (i < 90112) {
        int j = i - 24576; int o = j >> 7, c = j & 127;
        float s = bnvg[o] * rsqrtf(bnvv[o] + EPS);
        g_Wvt[c * OG + o] = Wv[o * 128 + c] * s;
    } else if (i < 106496) {
        int j = i - 90112; int o = j & 127, t = j >> 7;
        int g = t >> 5, m = t & 31;
        g_W2t[(g * MID + m) * COUT + o] = W2[(o * GCN + g) * MID + m];
    } else if (i < 106624) {
        int d = i - 106496;
        float s = bn1g[d] * rsqrtf(bn1v[d] + EPS);
        g_bke[d] = bn1b[d] - bn1m[d] * s;
    } else if (i < 106656) {
        int m = i - 106624;
        float s = bn2g[m] * rsqrtf(bn2v[m] + EPS);
        g_bh[m] = s * b1[m] + bn2b[m] - bn2m[m] * s;
    } else if (i < 107168) {
        int o = i - 106656;
        float s = bnvg[o] * rsqrtf(bnvv[o] + EPS);
        g_bv[o] = bnvb[o] - bnvm[o] * s;
    } else if (i < 111264) {
        g_M[i - 107168] = 0.f;
    } else if (i < 111392) {
        g_Sh[i - 111264] = 0.f;
    }
}

// ---------------- front kernel: ke (regs/smem only) + hq + hk in one pass ----------------
__global__ void __launch_bounds__(256) front_kernel(
    const float* __restrict__ X,
    float* __restrict__ hq_out, float* __restrict__ hk_out)
{
    extern __shared__ float fsm[];
    float* sX   = fsm;            // 4096
    float* sWk  = fsm + 4096;     // 8192
    float* sW1q = fsm + 12288;    // 2048
    float* sW1k = fsm;            // overlay of sX
    float* sKE  = fsm + 4096;     // overlay of sWk
    const int b   = blockIdx.y;
    const int hw0 = blockIdx.x * 64;
    const int tid = threadIdx.x;
    const int tx  = tid & 15;
    const int td  = tid >> 4;

    float keacc[8][4];
    float hqacc[2][4];
    #pragma unroll
    for (int j = 0; j < 8; j++)
        #pragma unroll
        for (int i = 0; i < 4; i++) keacc[j][i] = 0.f;
    #pragma unroll
    for (int j = 0; j < 2; j++)
        #pragma unroll
        for (int i = 0; i < 4; i++) hqacc[j][i] = 0.f;

    const float* Xb = X + (size_t)b * CC_IN * HW;
    for (int cc = 0; cc < 128; cc += 64) {
        for (int k = tid; k < 1024; k += 256) {
            int c = k >> 4, q = k & 15;
            *(float4*)&sX[c * 64 + q * 4] = *(const float4*)&Xb[(size_t)(cc + c) * HW + hw0 + q * 4];
        }
        for (int k = tid; k < 2048; k += 256) {
            int c = k >> 5, q = k & 31;
            *(float4*)&sWk[c * 128 + q * 4] = *(const float4*)&g_Wkt[(cc + c) * 128 + q * 4];
        }
        for (int k = tid; k < 512; k += 256) {
            int c = k >> 3, q = k & 7;
            *(float4*)&sW1q[c * 32 + q * 4] = *(const float4*)&g_W1qt[(cc + c) * 32 + q * 4];
        }
        __syncthreads();
        #pragma unroll 4
        for (int c = 0; c < 64; c++) {
            float4 xv = *(const float4*)&sX[c * 64 + 4 * tx];
            float4 w0 = *(const float4*)&sWk[c * 128 + 8 * td];
            float4 w1 = *(const float4*)&sWk[c * 128 + 8 * td + 4];
            keacc[0][0] = fmaf(w0.x, xv.x, keacc[0][0]); keacc[0][1] = fmaf(w0.x, xv.y, keacc[0][1]);
            keacc[0][2] = fmaf(w0.x, xv.z, keacc[0][2]); keacc[0][3] = fmaf(w0.x, xv.w, keacc[0][3]);
            keacc[1][0] = fmaf(w0.y, xv.x, keacc[1][0]); keacc[1][1] = fmaf(w0.y, xv.y, keacc[1][1]);
            keacc[1][2] = fmaf(w0.y, xv.z, keacc[1][2]); keacc[1][3] = fmaf(w0.y, xv.w, keacc[1][3]);
            keacc[2][0] = fmaf(w0.z, xv.x, keacc[2][0]); keacc[2][1] = fmaf(w0.z, xv.y, keacc[2][1]);
            keacc[2][2] = fmaf(w0.z, xv.z, keacc[2][2]); keacc[2][3] = fmaf(w0.z, xv.w, keacc[2][3]);
            keacc[3][0] = fmaf(w0.w, xv.x, keacc[3][0]); keacc[3][1] = fmaf(w0.w, xv.y, keacc[3][1]);
            keacc[3][2] = fmaf(w0.w, xv.z, keacc[3][2]); keacc[3][3] = fmaf(w0.w, xv.w, keacc[3][3]);
            keacc[4][0] = fmaf(w1.x, xv.x, keacc[4][0]); keacc[4][1] = fmaf(w1.x, xv.y, keacc[4][1]);
            keacc[4][2] = fmaf(w1.x, xv.z, keacc[4][2]); keacc[4][3] = fmaf(w1.x, xv.w, keacc[4][3]);
            keacc[5][0] = fmaf(w1.y, xv.x, keacc[5][0]); keacc[5][1] = fmaf(w1.y, xv.y, keacc[5][1]);
            keacc[5][2] = fmaf(w1.y, xv.z, keacc[5][2]); keacc[5][3] = fmaf(w1.y, xv.w, keacc[5][3]);
            keacc[6][0] = fmaf(w1.z, xv.x, keacc[6][0]); keacc[6][1] = fmaf(w1.z, xv.y, keacc[6][1]);
            keacc[6][2] = fmaf(w1.z, xv.z, keacc[6][2]); keacc[6][3] = fmaf(w1.z, xv.w, keacc[6][3]);
            keacc[7][0] = fmaf(w1.w, xv.x, keacc[7][0]); keacc[7][1] = fmaf(w1.w, xv.y, keacc[7][1]);
            keacc[7][2] = fmaf(w1.w, xv.z, keacc[7][2]); keacc[7][3] = fmaf(w1.w, xv.w, keacc[7][3]);
            float2 wq = *(const float2*)&sW1q[c * 32 + 2 * td];
            hqacc[0][0] = fmaf(wq.x, xv.x, hqacc[0][0]); hqacc[0][1] = fmaf(wq.x, xv.y, hqacc[0][1]);
            hqacc[0][2] = fmaf(wq.x, xv.z, hqacc[0][2]); hqacc[0][3] = fmaf(wq.x, xv.w, hqacc[0][3]);
            hqacc[1][0] = fmaf(wq.y, xv.x, hqacc[1][0]); hqacc[1][1] = fmaf(wq.y, xv.y, hqacc[1][1]);
            hqacc[1][2] = fmaf(wq.y, xv.z, hqacc[1][2]); hqacc[1][3] = fmaf(wq.y, xv.w, hqacc[1][3]);
        }
        __syncthreads();
    }
    #pragma unroll
    for (int j = 0; j < 2; j++) {
        int m = 2 * td + j;
        float4 r; r.x = hqacc[j][0]; r.y = hqacc[j][1]; r.z = hqacc[j][2]; r.w = hqacc[j][3];
        *(float4*)&hq_out[((size_t)b * MID + m) * HW + hw0 + 4 * tx] = r;
    }
    #pragma unroll
    for (int j = 0; j < 8; j++) {
        int d = 8 * td + j;
        float bsv = g_bke[d];
        float4 r;
        r.x = fmaxf(keacc[j][0] + bsv, 0.f); r.y = fmaxf(keacc[j][1] + bsv, 0.f);
        r.z = fmaxf(keacc[j][2] + bsv, 0.f); r.w = fmaxf(keacc[j][3] + bsv, 0.f);
        *(float4*)&sKE[d * 64 + 4 * tx] = r;
    }
    for (int k = tid; k < 1024; k += 256) {
        int c = k >> 3, q = k & 7;
        *(float4*)&sW1k[c * 32 + q * 4] = *(const float4*)&g_W1kt[c * 32 + q * 4];
    }
    __syncthreads();
    float hkacc[2][4];
    #pragma unroll
    for (int j = 0; j < 2; j++)
        #pragma unroll
        for (int i = 0; i < 4; i++) hkacc[j][i] = 0.f;
    #pragma unroll 4
    for (int c = 0; c < 128; c++) {
        float4 hv = *(const float4*)&sKE[c * 64 + 4 * tx];
        float2 w = *(const float2*)&sW1k[c * 32 + 2 * td];
        hkacc[0][0] = fmaf(w.x, hv.x, hkacc[0][0]); hkacc[0][1] = fmaf(w.x, hv.y, hkacc[0][1]);
        hkacc[0][2] = fmaf(w.x, hv.z, hkacc[0][2]); hkacc[0][3] = fmaf(w.x, hv.w, hkacc[0][3]);
        hkacc[1][0] = fmaf(w.y, hv.x, hkacc[1][0]); hkacc[1][1] = fmaf(w.y, hv.y, hkacc[1][1]);
        hkacc[1][2] = fmaf(w.y, hv.z, hkacc[1][2]); hkacc[1][3] = fmaf(w.y, hv.w, hkacc[1][3]);
    }
    #pragma unroll
    for (int j = 0; j < 2; j++) {
        int m = 2 * td + j;
        float4 r; r.x = hkacc[j][0]; r.y = hkacc[j][1]; r.z = hkacc[j][2]; r.w = hkacc[j][3];
        *(float4*)&hk_out[((size_t)b * MID + m) * HW + hw0 + 4 * tx] = r;
    }
}

// ---------------- pointwise-conv GEMM (Wv): 128 threads, 8 d x 4 px ----------------
template<int DTILE, bool RELU>
__global__ void __launch_bounds__(128) pw_conv_kernel(
    const float* __restrict__ X, const float* __restrict__ Wt,
    const float* __restrict__ bias, float* __restrict__ Y, int Dtot)
{
    constexpr int PX = 64;
    constexpr int CCH = 64;
    constexpr int DN = DTILE / 8;
    __shared__ float sX[CCH * PX];
    __shared__ float sW[CCH * DTILE];
    const int b   = blockIdx.z;
    const int hw0 = blockIdx.x * PX;
    const int d0  = blockIdx.y * DTILE;
    const int tid = threadIdx.x;
    const int tx  = tid & 15;
    const int td  = tid >> 4;
    float acc[DN][4];
    #pragma unroll
    for (int j = 0; j < DN; j++)
        #pragma unroll
        for (int i = 0; i < 4; i++) acc[j][i] = 0.f;
    const float* Xb = X + (size_t)b * CC_IN * HW;
    for (int cc = 0; cc < CC_IN; cc += CCH) {
        for (int k = tid; k < CCH * PX / 4; k += 128) {
            int c = k >> 4, q = k & 15;
            *(float4*)&sX[c * 64 + q * 4] = *(const float4*)&Xb[(size_t)(cc + c) * HW + hw0 + q * 4];
        }
        for (int k = tid; k < CCH * DTILE / 4; k += 128) {
            int c = k / (DTILE / 4), q = k % (DTILE / 4);
            *(float4*)&sW[c * DTILE + q * 4] = *(const float4*)&Wt[(size_t)(cc + c) * Dtot + d0 + q * 4];
        }
        __syncthreads();
        #pragma unroll 4
        for (int c = 0; c < CCH; c++) {
            float4 xv = *(const float4*)&sX[c * 64 + 4 * tx];
            float4 w0 = *(const float4*)&sW[c * DTILE + DN * td];
            acc[0][0] = fmaf(w0.x, xv.x, acc[0][0]); acc[0][1] = fmaf(w0.x, xv.y, acc[0][1]);
            acc[0][2] = fmaf(w0.x, xv.z, acc[0][2]); acc[0][3] = fmaf(w0.x, xv.w, acc[0][3]);
            acc[1][0] = fmaf(w0.y, xv.x, acc[1][0]); acc[1][1] = fmaf(w0.y, xv.y, acc[1][1]);
            acc[1][2] = fmaf(w0.y, xv.z, acc[1][2]); acc[1][3] = fmaf(w0.y, xv.w, acc[1][3]);
            acc[2][0] = fmaf(w0.z, xv.x, acc[2][0]); acc[2][1] = fmaf(w0.z, xv.y, acc[2][1]);
            acc[2][2] = fmaf(w0.z, xv.z, acc[2][2]); acc[2][3] = fmaf(w0.z, xv.w, acc[2][3]);
            acc[3][0] = fmaf(w0.w, xv.x, acc[3][0]); acc[3][1] = fmaf(w0.w, xv.y, acc[3][1]);
            acc[3][2] = fmaf(w0.w, xv.z, acc[3][2]); acc[3][3] = fmaf(w0.w, xv.w, acc[3][3]);
            if (DN == 8) {
                float4 w1 = *(const float4*)&sW[c * DTILE + DN * td + 4];
                acc[4][0] = fmaf(w1.x, xv.x, acc[4][0]); acc[4][1] = fmaf(w1.x, xv.y, acc[4][1]);
                acc[4][2] = fmaf(w1.x, xv.z, acc[4][2]); acc[4][3] = fmaf(w1.x, xv.w, acc[4][3]);
                acc[5][0] = fmaf(w1.y, xv.x, acc[5][0]); acc[5][1] = fmaf(w1.y, xv.y, acc[5][1]);
                acc[5][2] = fmaf(w1.y, xv.z, acc[5][2]); acc[5][3] = fmaf(w1.y, xv.w, acc[5][3]);
                acc[6][0] = fmaf(w1.z, xv.x, acc[6][0]); acc[6][1] = fmaf(w1.z, xv.y, acc[6][1]);
                acc[6][2] = fmaf(w1.z, xv.z, acc[6][2]); acc[6][3] = fmaf(w1.z, xv.w, acc[6][3]);
                acc[7][0] = fmaf(w1.w, xv.x, acc[7][0]); acc[7][1] = fmaf(w1.w, xv.y, acc[7][1]);
                acc[7][2] = fmaf(w1.w, xv.z, acc[7][2]); acc[7][3] = fmaf(w1.w, xv.w, acc[7][3]);
            }
        }
        __syncthreads();
    }
    #pragma unroll
    for (int j = 0; j < DN; j++) {
        int d = d0 + td * DN + j;
        float bsv = bias ? bias[d] : 0.f;
        float4 r;
        r.x = acc[j][0] + bsv; r.y = acc[j][1] + bsv;
        r.z = acc[j][2] + bsv; r.w = acc[j][3] + bsv;
        if (RELU) {
            r.x = fmaxf(r.x, 0.f); r.y = fmaxf(r.y, 0.f);
            r.z = fmaxf(r.z, 0.f); r.w = fmaxf(r.w, 0.f);
        }
        *(float4*)&Y[((size_t)b * Dtot + d) * HW + hw0 + 4 * tx] = r;
    }
}

// ---------------- stats: build 3 dj planes once, SYRK, atomics ----------------
__global__ void __launch_bounds__(256) stats_gram_kernel(
    const float* __restrict__ hq, const float* __restrict__ hk,
    const float* __restrict__ bh,
    float* __restrict__ M, float* __restrict__ Sh)
{
    __shared__ float s_hq[32 * 56];
    __shared__ float s_hk[32 * 58];
    __shared__ float sHp [3 * 56 * 32];
    __shared__ float sSh [32];
    __shared__ float sM  [1024];
    const int y  = blockIdx.x;
    const int di = blockIdx.y;
    const int b  = blockIdx.z;
    const int tid = threadIdx.x;
    const int mloc = tid & 31;
    if (tid < 32) sSh[tid] = 0.f;
    for (int k = tid; k < 1024; k += 256) sM[k] = 0.f;
    for (int k = tid; k < 1792; k += 256) {
        int m = k / 56, x = k % 56;
        s_hq[m * 56 + x] = hq[((size_t)b * MID + m) * HW + y * WW + x];
    }
    const int yk = y + di - 1;
    const bool rowin = (yk >= 0 && yk < HH);
    for (int k = tid; k < 1856; k += 256) {
        int m = k / 58, xi = k % 58;
        int xp = xi - 1;
        s_hk[k] = (rowin && xp >= 0 && xp < WW)
                 ? hk[((size_t)b * MID + m) * HW + yk * WW + xp] : 0.f;
    }
    __syncthreads();
    const float bhm = bh[mloc];
    float shsum = 0.f;
    for (int k = tid; k < 5376; k += 256) {
        int xdj = k >> 5;
        int dj = xdj / 56, x = xdj % 56;
        float v = fmaxf(s_hq[mloc * 56 + x] + s_hk[mloc * 58 + x + dj] + bhm, 0.f);
        sHp[k] = v;
        shsum += v;
    }
    __syncthreads();
    const int combo = tid & 63;
    const int it = combo & 7, jt = combo >> 3;
    const int pg = tid >> 6;
    float accM[4][4];
    #pragma unroll
    for (int a = 0; a < 4; a++)
        #pragma unroll
        for (int c = 0; c < 4; c++) accM[a][c] = 0.f;
    #pragma unroll 2
    for (int px = pg * 42; px < pg * 42 + 42; px++) {
        float4 hi = *(const float4*)&sHp[px * 32 + it * 4];
        float4 hj = *(const float4*)&sHp[px * 32 + jt * 4];
        accM[0][0] = fmaf(hi.x, hj.x, accM[0][0]); accM[0][1] = fmaf(hi.x, hj.y, accM[0][1]);
        accM[0][2] = fmaf(hi.x, hj.z, accM[0][2]); accM[0][3] = fmaf(hi.x, hj.w, accM[0][3]);
        accM[1][0] = fmaf(hi.y, hj.x, accM[1][0]); accM[1][1] = fmaf(hi.y, hj.y, accM[1][1]);
        accM[1][2] = fmaf(hi.y, hj.z, accM[1][2]); accM[1][3] = fmaf(hi.y, hj.w, accM[1][3]);
        accM[2][0] = fmaf(hi.z, hj.x, accM[2][0]); accM[2][1] = fmaf(hi.z, hj.y, accM[2][1]);
        accM[2][2] = fmaf(hi.z, hj.z, accM[2][2]); accM[2][3] = fmaf(hi.z, hj.w, accM[2][3]);
        accM[3][0] = fmaf(hi.w, hj.x, accM[3][0]); accM[3][1] = fmaf(hi.w, hj.y, accM[3][1]);
        accM[3][2] = fmaf(hi.w, hj.z, accM[3][2]); accM[3][3] = fmaf(hi.w, hj.w, accM[3][3]);
    }
    atomicAdd(&sSh[mloc], shsum);
    #pragma unroll
    for (int a = 0; a < 4; a++)
        #pragma unroll
        for (int c = 0; c < 4; c++)
            atomicAdd(&sM[(it * 4 + a) * 32 + jt * 4 + c], accM[a][c]);
    __syncthreads();
    if (tid < 32) atomicAdd(&Sh[b * 32 + tid], sSh[tid]);
    for (int k = tid; k < 1024; k += 256) atomicAdd(&M[b * 1024 + k], sM[k]);
}

// ---------------- GroupNorm stats -> precomputed GN affine (c1, c0) ----------------
__global__ void stats_kernel(const float* __restrict__ W2, const float* __restrict__ b2,
                             const float* __restrict__ gng, const float* __restrict__ gnb,
                             const float* __restrict__ M, const float* __restrict__ Sh,
                             float* __restrict__ c1out, float* __restrict__ c0out)
{
    int b = blockIdx.x, o = threadIdx.x;
    __shared__ float sM[1024], sSh[32];
    for (int k = o; k < 1024; k += 128) sM[k] = M[b * 1024 + k];
    if (o < 32) sSh[o] = Sh[b * 32 + o];
    __syncthreads();
    float S1 = 0.f, S2 = 0.f;
    const float NPf = (float)NPQ;
    for (int g = 0; g < GCN; g++) {
        int og = o * GCN + g;
        float w[32];
        #pragma unroll
        for (int m = 0; m < 32; m++) w[m] = W2[og * 32 + m];
        float d1 = 0.f;
        #pragma unroll
        for (int m = 0; m < 32; m++) d1 = fmaf(w[m], sSh[m], d1);
        float q = 0.f;
        for (int i2 = 0; i2 < 32; i2++) {
            float ti = 0.f;
            #pragma unroll
            for (int j = 0; j < 32; j++) ti = fmaf(sM[i2 * 32 + j], w[j], ti);
            q = fmaf(w[i2], ti, q);
        }
        float bbv = b2[og];
        S1 += d1 + bbv * NPf;
        S2 += q + 2.f * bbv * d1 + bbv * bbv * NPf;
    }
    const float N = (float)(GCN * NPQ);
    float m_ = S1 / N;
    float var = S2 / N - m_ * m_;
    float rinv = rsqrtf(var + EPS);
    #pragma unroll
    for (int g = 0; g < GCN; g++) {
        int og = o * GCN + g;
        float c1 = rinv * gng[og];
        float c0 = c1 * b2[og] + gnb[og] - m_ * c1;
        c1out[b * OG + og] = c1;
        c0out[b * OG + og] = c0;
    }
}

// ---------------- main fused kernel (R7 structure + c1/c0 + bh-fold) ----------------
// grid (7, 14, B*2). 128 threads, 4 o x 4 px per thread, 64 couts per block.
// smem: sH 9216 | sV 3968 | sWt 2176 = 15360 fl = 61440 B -> 3 blocks/SM
__global__ void __launch_bounds__(128) main_kernel(
    const float* __restrict__ hq, const float* __restrict__ hk,
    const float* __restrict__ v,
    const float* __restrict__ W2t,
    const float* __restrict__ c1arr, const float* __restrict__ c0arr,
    const float* __restrict__ bh, float* __restrict__ out)
{
    extern __shared__ float smem[];
    float* sH  = smem;                 // 9216
    float* sV  = smem + 9216;          // 3968
    float* sWt = smem + 13184;         // 2176
    float* s_hq = sV;                  // staging overlay (1024)
    float* s_hk = sV + 1024;           // staging overlay (1920)
    const int bz  = blockIdx.z;
    const int b   = bz >> 1;
    const int ob0 = (bz & 1) * 64;
    const int x0  = blockIdx.x * 8;
    const int y0  = blockIdx.y * 4;
    const int tid = threadIdx.x;
    const int tq  = tid & 7;
    const int to  = tid >> 3;
    const int ly  = tq >> 1;
    const int lx0 = (tq & 1) * 4;

    // stage hq (+bh folded) and hk halo
    for (int k = tid; k < 1024; k += 128) {
        int m = k >> 5, px = k & 31, lyy = px >> 3, lxx = px & 7;
        s_hq[k] = hq[((size_t)b * MID + m) * HW + (y0 + lyy) * WW + x0 + lxx] + bh[m];
    }
    for (int k = tid; k < 1920; k += 128) {
        int m = k / 60, s = k % 60, yy = s / 10, xx = s % 10;
        int gy = y0 - 1 + yy, gx = x0 - 1 + xx;
        s_hk[k] = (gy >= 0 && gy < HH && gx >= 0 && gx < WW)
                  ? hk[((size_t)b * MID + m) * HW + gy * WW + gx] : 0.f;
    }
    __syncthreads();
    for (int k = tid; k < 9216; k += 128) {
        int p = k >> 10, m = (k >> 5) & 31, px = k & 31;
        int lyy = px >> 3, lxx = px & 7;
        int di = p / 3, dj = p % 3;
        float val = s_hq[m * 32 + px] + s_hk[m * 60 + (lyy + di) * 10 + (lxx + dj)];
        sH[k] = fmaxf(val, 0.f);
    }

    float acc[4][4];
    #pragma unroll
    for (int oo = 0; oo < 4; oo++)
        #pragma unroll
        for (int i = 0; i < 4; i++) acc[oo][i] = 0.f;

    const float* vb = v + (size_t)b * OG * HW;
    for (int g = 0; g < GCN; g++) {
        __syncthreads();
        for (int k = tid; k < 64 * 60; k += 128) {
            int o = k / 60, s = k % 60, yy = s / 10, xx = s % 10;
            int gy = y0 - 1 + yy, gx = x0 - 1 + xx;
            float val = 0.f;
            if (gy >= 0 && gy < HH && gx >= 0 && gx < WW)
                val = vb[(size_t)((ob0 + o) * GCN + g) * HW + gy * WW + gx];
            sV[o * 62 + s] = val;
        }
        for (int k = tid; k < 2048; k += 128) {
            int m = k >> 6, o = k & 63;
            sWt[m * 68 + o] = W2t[(g * MID + m) * COUT + ob0 + o];
        }
        __syncthreads();

        float c1r[4], c0r[4];
        #pragma unroll
        for (int oo = 0; oo < 4; oo++) {
            int og = (ob0 + to * 4 + oo) * GCN + g;
            c1r[oo] = c1arr[b * OG + og];
            c0r[oo] = c0arr[b * OG + og];
        }

        #pragma unroll
        for (int sweep = 0; sweep < 3; sweep++) {
            float aacc[3][4][4];
            #pragma unroll
            for (int pp = 0; pp < 3; pp++)
                #pragma unroll
                for (int oo = 0; oo < 4; oo++)
                    #pragma unroll
                    for (int i = 0; i < 4; i++) aacc[pp][oo][i] = 0.f;
            #pragma unroll 8
            for (int m = 0; m < 32; m++) {
                float4 w = *(const float4*)&sWt[m * 68 + 4 * to];
                #pragma unroll
                for (int pp = 0; pp < 3; pp++) {
                    float4 hv = *(const float4*)&sH[((sweep * 3 + pp) << 10) + (m << 5) + 4 * tq];
                    float* a0 = &aacc[pp][0][0];
                    a0[0]  = fmaf(w.x, hv.x, a0[0]);  a0[1]  = fmaf(w.x, hv.y, a0[1]);
                    a0[2]  = fmaf(w.x, hv.z, a0[2]);  a0[3]  = fmaf(w.x, hv.w, a0[3]);
                    a0[4]  = fmaf(w.y, hv.x, a0[4]);  a0[5]  = fmaf(w.y, hv.y, a0[5]);
                    a0[6]  = fmaf(w.y, hv.z, a0[6]);  a0[7]  = fmaf(w.y, hv.w, a0[7]);
                    a0[8]  = fmaf(w.z, hv.x, a0[8]);  a0[9]  = fmaf(w.z, hv.y, a0[9]);
                    a0[10] = fmaf(w.z, hv.z, a0[10]); a0[11] = fmaf(w.z, hv.w, a0[11]);
                    a0[12] = fmaf(w.w, hv.x, a0[12]); a0[13] = fmaf(w.w, hv.y, a0[13]);
                    a0[14] = fmaf(w.w, hv.z, a0[14]); a0[15] = fmaf(w.w, hv.w, a0[15]);
                }
            }
            #pragma unroll
            for (int pp = 0; pp < 3; pp++) {
                #pragma unroll
                for (int oo = 0; oo < 4; oo++) {
                    float c1 = c1r[oo], c0 = c0r[oo];
                    int ol = to * 4 + oo;
                    #pragma unroll
                    for (int i = 0; i < 4; i++) {
                        float Vv = sV[ol * 62 + (ly + sweep) * 10 + (lx0 + i + pp)];
                        float t = fmaf(c1, aacc[pp][oo][i], c0);
                        acc[oo][i] = fmaf(t, Vv, acc[oo][i]);
                    }
                }
            }
        }
    }
    #pragma unroll
    for (int oo = 0; oo < 4; oo++) {
        float4 r;
        r.x = acc[oo][0]; r.y = acc[oo][1]; r.z = acc[oo][2]; r.w = acc[oo][3];
        *(float4*)&out[((size_t)b * COUT + ob0 + to * 4 + oo) * HW + (y0 + ly) * WW + x0 + lx0] = r;
    }
}

// ---------------- launch ----------------
extern "C" void kernel_launch(void* const* d_in, const int* in_sizes, int n_in,
                              void* d_out, int out_size)
{
    const float* x     = (const float*)d_in[0];
    const float* Wk    = (const float*)d_in[1];
    const float* bn1g  = (const float*)d_in[2];
    const float* bn1b  = (const float*)d_in[3];
    const float* bn1m  = (const float*)d_in[4];
    const float* bn1v  = (const float*)d_in[5];
    const float* W1    = (const float*)d_in[6];
    const float* b1    = (const float*)d_in[7];
    const float* bn2g  = (const float*)d_in[8];
    const float* bn2b  = (const float*)d_in[9];
    const float* bn2m  = (const float*)d_in[10];
    const float* bn2v  = (const float*)d_in[11];
    const float* W2    = (const float*)d_in[12];
    const float* b2    = (const float*)d_in[13];
    const float* gng   = (const float*)d_in[14];
    const float* gnb   = (const float*)d_in[15];
    const float* Wv    = (const float*)d_in[16];
    const float* bnvg  = (const float*)d_in[17];
    const float* bnvb  = (const float*)d_in[18];
    const float* bnvm  = (const float*)d_in[19];
    const float* bnvv  = (const float*)d_in[20];
    float* out = (float*)d_out;

    float *vv, *hq, *hk, *pM, *pSh, *pc1, *pc0;
    float *pWvt, *pW2t, *pbv, *pbh;
    cudaGetSymbolAddress((void**)&vv,    g_v);
    cudaGetSymbolAddress((void**)&hq,    g_hq);
    cudaGetSymbolAddress((void**)&hk,    g_hk);
    cudaGetSymbolAddress((void**)&pM,    g_M);
    cudaGetSymbolAddress((void**)&pSh,   g_Sh);
    cudaGetSymbolAddress((void**)&pc1,   g_c1);
    cudaGetSymbolAddress((void**)&pc0,   g_c0);
    cudaGetSymbolAddress((void**)&pWvt,  g_Wvt);
    cudaGetSymbolAddress((void**)&pW2t,  g_W2t);
    cudaGetSymbolAddress((void**)&pbv,   g_bv);
    cudaGetSymbolAddress((void**)&pbh,   g_bh);

    static cudaStream_t s2 = nullptr;
    static cudaEvent_t evFork = nullptr, evJoin = nullptr;
    static bool init_done = false;
    if (!init_done) {
        cudaFuncSetAttribute(main_kernel,  cudaFuncAttributeMaxDynamicSharedMemorySize, 61440);
        cudaFuncSetAttribute(front_kernel, cudaFuncAttributeMaxDynamicSharedMemorySize, 57344);
        cudaStreamCreateWithFlags(&s2, cudaStreamNonBlocking);
        cudaEventCreateWithFlags(&evFork, cudaEventDisableTiming);
        cudaEventCreateWithFlags(&evJoin, cudaEventDisableTiming);
        init_done = true;
    }

    fold_kernel<<<(111392 + 255) / 256, 256>>>(Wk, bn1g, bn1b, bn1m, bn1v,
                                               W1, b1, bn2g, bn2b, bn2m, bn2v,
                                               W2, Wv, bnvg, bnvb, bnvm, bnvv);
    // fork: Wv GEMM runs on s2 concurrently with front + stats chain
    cudaEventRecord(evFork, 0);
    cudaStreamWaitEvent(s2, evFork, 0);
    pw_conv_kernel<64, false><<<dim3(49, 8, BB), 128, 0, s2>>>(x, pWvt, pbv, vv, OG);
    cudaEventRecord(evJoin, s2);

    front_kernel<<<dim3(49, BB), 256, 57344>>>(x, hq, hk);
    stats_gram_kernel<<<dim3(56, 3, BB), 256>>>(hq, hk, pbh, pM, pSh);
    stats_kernel<<<BB, 128>>>(W2, b2, gng, gnb, pM, pSh, pc1, pc0);

    // join: main needs v from s2
    cudaStreamWaitEvent(0, evJoin, 0);
    main_kernel<<<dim3(7, 14, BB * 2), 128, 61440>>>(hq, hk, vv, pW2t, pc1, pc0, pbh, out);
}